// round 5
// baseline (speedup 1.0000x reference)
#include <cuda_runtime.h>

// ---------------------------------------------------------------------------
// GCN 2-layer, CSR-based (atomic-free aggregation):
//   build dst-CSR (count -> scan -> fill)
//   h   = ReLU(BN(sum_e norm_e*xw1[src] + dinv^2*xw1[i] + b1))   [warp/node]
//   out = sum_e norm_e*xw2[src] + dinv^2*xw2[i] + b2             [warp/node]
// edge_index is int32 [2, E] (JAX x64-off demotes int64).
// ---------------------------------------------------------------------------

#define N_MAX 50000
#define E_MAX 800000
#define D1 128
#define D2 64
#define SCAN_B 1024

__device__ float g_deg   [N_MAX];
__device__ float g_dinv  [N_MAX];
__device__ int   g_cnt   [N_MAX];
__device__ int   g_rstart[N_MAX];
__device__ int   g_cursor[N_MAX];
__device__ int   g_bsum  [64];
__device__ int   g_csrc  [E_MAX];
__device__ float g_cnorm [E_MAX];
__device__ float g_xw1 [(size_t)N_MAX * D1];
__device__ float g_h   [(size_t)N_MAX * D1];
__device__ float g_xw2 [(size_t)N_MAX * D2];

// ------------------------------ prep kernels -------------------------------

__global__ void k_init(float* deg, int* cnt, int n) {
    int i = blockIdx.x * blockDim.x + threadIdx.x;
    if (i < n) { deg[i] = 1.0f; cnt[i] = 0; }    // self-loop weight 1
}

__global__ void k_count(const int* __restrict__ ei, const float* __restrict__ w,
                        float* __restrict__ deg, int* __restrict__ cnt, int e) {
    int i = blockIdx.x * blockDim.x + threadIdx.x;
    if (i >= e) return;
    int d = ei[e + i];
    atomicAdd(&cnt[d], 1);
    atomicAdd(&deg[d], w[i]);
}

__global__ void k_dinv(const float* __restrict__ deg, float* __restrict__ dinv, int n) {
    int i = blockIdx.x * blockDim.x + threadIdx.x;
    if (i < n) {
        float d = deg[i];
        dinv[i] = d > 0.f ? rsqrtf(d) : 0.f;
    }
}

// exclusive scan of cnt -> rstart (3-phase)
__global__ void k_scan1(const int* __restrict__ cnt, int* __restrict__ rstart,
                        int* __restrict__ bsum, int n) {
    __shared__ int sh[SCAN_B];
    int i = blockIdx.x * SCAN_B + threadIdx.x;
    int v = (i < n) ? cnt[i] : 0;
    sh[threadIdx.x] = v;
    __syncthreads();
    for (int off = 1; off < SCAN_B; off <<= 1) {
        int t = (threadIdx.x >= off) ? sh[threadIdx.x - off] : 0;
        __syncthreads();
        sh[threadIdx.x] += t;
        __syncthreads();
    }
    if (i < n) rstart[i] = sh[threadIdx.x] - v;          // exclusive
    if (threadIdx.x == SCAN_B - 1) bsum[blockIdx.x] = sh[SCAN_B - 1];
}

__global__ void k_scan2(int* __restrict__ bsum, int nb) {
    __shared__ int sh[64];
    int v = (threadIdx.x < nb) ? bsum[threadIdx.x] : 0;
    sh[threadIdx.x] = v;
    __syncthreads();
    for (int off = 1; off < 64; off <<= 1) {
        int t = (threadIdx.x >= off) ? sh[threadIdx.x - off] : 0;
        __syncthreads();
        sh[threadIdx.x] += t;
        __syncthreads();
    }
    if (threadIdx.x < nb) bsum[threadIdx.x] = sh[threadIdx.x] - v;   // exclusive
}

__global__ void k_scan3(int* __restrict__ rstart, const int* __restrict__ bsum,
                        int* __restrict__ cursor, int n) {
    int i = blockIdx.x * blockDim.x + threadIdx.x;
    if (i < n) {
        int v = rstart[i] + bsum[i >> 10];
        rstart[i] = v;
        cursor[i] = v;
    }
}

__global__ void k_fill(const int* __restrict__ ei, const float* __restrict__ w,
                       const float* __restrict__ dinv,
                       int* __restrict__ cursor,
                       int* __restrict__ csrc, float* __restrict__ cnorm, int e) {
    int i = blockIdx.x * blockDim.x + threadIdx.x;
    if (i >= e) return;
    int s = ei[i];
    int d = ei[e + i];
    int pos = atomicAdd(&cursor[d], 1);
    csrc[pos]  = s;
    cnorm[pos] = dinv[s] * w[i] * dinv[d];
}

// -------------------------------- GEMM -------------------------------------
// Y[n, COLS] = X[n, 128] @ W[128, COLS].  W in smem; float4 W loads:
// 4 FFMA per LDS.128 -> FFMA-bound, not LDS-bound.

template <int COLS>
__global__ void __launch_bounds__(256) k_gemm(const float* __restrict__ X,
                                              const float* __restrict__ W,
                                              float* __restrict__ Y, int n) {
    extern __shared__ float Wsh[];               // 128 * COLS floats
    constexpr int TPR = COLS / 4;                // threads per row (32 or 16)
    constexpr int RPI = 256 / TPR;               // rows per iteration (8 or 16)
    constexpr int ROWS_BLK = 64;
    for (int i = threadIdx.x; i < 128 * COLS / 4; i += 256)
        ((float4*)Wsh)[i] = ((const float4*)W)[i];
    __syncthreads();

    int col0 = (threadIdx.x % TPR) * 4;
    int rsub = threadIdx.x / TPR;
    int row0 = blockIdx.x * ROWS_BLK;
    int rend = min(row0 + ROWS_BLK, n);

    for (int r = row0 + rsub; r < rend; r += RPI) {
        const float4* xr = (const float4*)(X + (size_t)r * 128);
        float4 acc = make_float4(0.f, 0.f, 0.f, 0.f);
#pragma unroll
        for (int k4 = 0; k4 < 32; k4++) {
            float4 xv = xr[k4];
#pragma unroll
            for (int u = 0; u < 4; u++) {
                float xs = (u == 0) ? xv.x : (u == 1) ? xv.y : (u == 2) ? xv.z : xv.w;
                float4 wv = *(const float4*)&Wsh[(k4 * 4 + u) * COLS + col0];
                acc.x = fmaf(xs, wv.x, acc.x);
                acc.y = fmaf(xs, wv.y, acc.y);
                acc.z = fmaf(xs, wv.z, acc.z);
                acc.w = fmaf(xs, wv.w, acc.w);
            }
        }
        *(float4*)(Y + (size_t)r * COLS + col0) = acc;
    }
}

// --------------------------- CSR aggregation -------------------------------
// Layer 1: warp per node; lane owns 4 channels (float4). Fused self-loop,
// bias, BN (running stats), ReLU.

__global__ void __launch_bounds__(256) k_agg1(
        const float* __restrict__ xw, const int* __restrict__ csrc,
        const float* __restrict__ cnorm, const int* __restrict__ rstart,
        const int* __restrict__ cnt, const float* __restrict__ dinv,
        const float* __restrict__ b1, const float* __restrict__ gamma,
        const float* __restrict__ beta, const float* __restrict__ rmean,
        const float* __restrict__ rvar,
        float* __restrict__ h, int n) {
    int node = (blockIdx.x * blockDim.x + threadIdx.x) >> 5;
    if (node >= n) return;
    int lane = threadIdx.x & 31;
    int s0 = rstart[node];
    int c  = cnt[node];

    float4 acc = make_float4(0.f, 0.f, 0.f, 0.f);
    int k = 0;
    for (; k + 2 <= c; k += 2) {                 // unroll 2 for MLP
        int   sA = csrc[s0 + k],      sB = csrc[s0 + k + 1];
        float nA = cnorm[s0 + k],     nB = cnorm[s0 + k + 1];
        float4 vA = *(const float4*)(xw + (size_t)sA * D1 + lane * 4);
        float4 vB = *(const float4*)(xw + (size_t)sB * D1 + lane * 4);
        acc.x = fmaf(nA, vA.x, acc.x); acc.y = fmaf(nA, vA.y, acc.y);
        acc.z = fmaf(nA, vA.z, acc.z); acc.w = fmaf(nA, vA.w, acc.w);
        acc.x = fmaf(nB, vB.x, acc.x); acc.y = fmaf(nB, vB.y, acc.y);
        acc.z = fmaf(nB, vB.z, acc.z); acc.w = fmaf(nB, vB.w, acc.w);
    }
    if (k < c) {
        int   s = csrc[s0 + k];
        float nv = cnorm[s0 + k];
        float4 v = *(const float4*)(xw + (size_t)s * D1 + lane * 4);
        acc.x = fmaf(nv, v.x, acc.x); acc.y = fmaf(nv, v.y, acc.y);
        acc.z = fmaf(nv, v.z, acc.z); acc.w = fmaf(nv, v.w, acc.w);
    }

    float di = dinv[node];
    float sl = di * di;
    float4 xv = *(const float4*)(xw + (size_t)node * D1 + lane * 4);
    int c4 = lane * 4;
    float4 bb = *(const float4*)(b1 + c4);
    float4 g  = *(const float4*)(gamma + c4);
    float4 be = *(const float4*)(beta + c4);
    float4 m  = *(const float4*)(rmean + c4);
    float4 vv = *(const float4*)(rvar + c4);
    float4 o;
    o.x = fmaxf((acc.x + sl * xv.x + bb.x - m.x) * rsqrtf(vv.x + 1e-5f) * g.x + be.x, 0.f);
    o.y = fmaxf((acc.y + sl * xv.y + bb.y - m.y) * rsqrtf(vv.y + 1e-5f) * g.y + be.y, 0.f);
    o.z = fmaxf((acc.z + sl * xv.z + bb.z - m.z) * rsqrtf(vv.z + 1e-5f) * g.z + be.z, 0.f);
    o.w = fmaxf((acc.w + sl * xv.w + bb.w - m.w) * rsqrtf(vv.w + 1e-5f) * g.w + be.w, 0.f);
    *(float4*)(h + (size_t)node * D1 + c4) = o;
}

// Layer 2: warp per node; lane owns 2 channels (float2). Fused self + bias
// straight into d_out.

__global__ void __launch_bounds__(256) k_agg2(
        const float* __restrict__ xw, const int* __restrict__ csrc,
        const float* __restrict__ cnorm, const int* __restrict__ rstart,
        const int* __restrict__ cnt, const float* __restrict__ dinv,
        const float* __restrict__ b2,
        float* __restrict__ out, int n) {
    int node = (blockIdx.x * blockDim.x + threadIdx.x) >> 5;
    if (node >= n) return;
    int lane = threadIdx.x & 31;
    int s0 = rstart[node];
    int c  = cnt[node];

    float2 acc = make_float2(0.f, 0.f);
    int k = 0;
    for (; k + 2 <= c; k += 2) {
        int   sA = csrc[s0 + k],      sB = csrc[s0 + k + 1];
        float nA = cnorm[s0 + k],     nB = cnorm[s0 + k + 1];
        float2 vA = *(const float2*)(xw + (size_t)sA * D2 + lane * 2);
        float2 vB = *(const float2*)(xw + (size_t)sB * D2 + lane * 2);
        acc.x = fmaf(nA, vA.x, acc.x); acc.y = fmaf(nA, vA.y, acc.y);
        acc.x = fmaf(nB, vB.x, acc.x); acc.y = fmaf(nB, vB.y, acc.y);
    }
    if (k < c) {
        int   s = csrc[s0 + k];
        float nv = cnorm[s0 + k];
        float2 v = *(const float2*)(xw + (size_t)s * D2 + lane * 2);
        acc.x = fmaf(nv, v.x, acc.x); acc.y = fmaf(nv, v.y, acc.y);
    }

    float di = dinv[node];
    float sl = di * di;
    float2 xv = *(const float2*)(xw + (size_t)node * D2 + lane * 2);
    float2 bb = *(const float2*)(b2 + lane * 2);
    float2 o;
    o.x = acc.x + sl * xv.x + bb.x;
    o.y = acc.y + sl * xv.y + bb.y;
    *(float2*)(out + (size_t)node * D2 + lane * 2) = o;
}

// ------------------------------- launcher ----------------------------------

extern "C" void kernel_launch(void* const* d_in, const int* in_sizes, int n_in,
                              void* d_out, int out_size) {
    const float* x     = (const float*)d_in[0];
    const int*   ei    = (const int*)d_in[1];     // int32 [2, E]
    const float* ew    = (const float*)d_in[2];
    const float* W1    = (const float*)d_in[3];
    const float* b1    = (const float*)d_in[4];
    const float* gamma = (const float*)d_in[5];
    const float* beta  = (const float*)d_in[6];
    const float* rmean = (const float*)d_in[7];
    const float* rvar  = (const float*)d_in[8];
    const float* W2    = (const float*)d_in[9];
    const float* b2    = (const float*)d_in[10];
    float* out = (float*)d_out;

    int n = in_sizes[0] / D1;
    int e = in_sizes[2];

    float *deg, *dinv, *cnorm, *xw1, *h, *xw2;
    int *cnt, *rstart, *cursor, *bsum, *csrc;
    cudaGetSymbolAddress((void**)&deg,    g_deg);
    cudaGetSymbolAddress((void**)&dinv,   g_dinv);
    cudaGetSymbolAddress((void**)&cnt,    g_cnt);
    cudaGetSymbolAddress((void**)&rstart, g_rstart);
    cudaGetSymbolAddress((void**)&cursor, g_cursor);
    cudaGetSymbolAddress((void**)&bsum,   g_bsum);
    cudaGetSymbolAddress((void**)&csrc,   g_csrc);
    cudaGetSymbolAddress((void**)&cnorm,  g_cnorm);
    cudaGetSymbolAddress((void**)&xw1,    g_xw1);
    cudaGetSymbolAddress((void**)&h,      g_h);
    cudaGetSymbolAddress((void**)&xw2,    g_xw2);

    cudaFuncSetAttribute(k_gemm<D1>, cudaFuncAttributeMaxDynamicSharedMemorySize,
                         128 * D1 * (int)sizeof(float));
    cudaFuncSetAttribute(k_gemm<D2>, cudaFuncAttributeMaxDynamicSharedMemorySize,
                         128 * D2 * (int)sizeof(float));

    const int T = 256;
    auto cdiv = [](long long a, long long b) { return (int)((a + b - 1) / b); };
    int nscan = cdiv(n, SCAN_B);

    // --- degree + CSR build ---
    k_init <<<cdiv(n, T), T>>>(deg, cnt, n);
    k_count<<<cdiv(e, T), T>>>(ei, ew, deg, cnt, e);
    k_dinv <<<cdiv(n, T), T>>>(deg, dinv, n);
    k_scan1<<<nscan, SCAN_B>>>(cnt, rstart, bsum, n);
    k_scan2<<<1, 64>>>(bsum, nscan);
    k_scan3<<<cdiv(n, T), T>>>(rstart, bsum, cursor, n);
    k_fill <<<cdiv(e, T), T>>>(ei, ew, dinv, cursor, csrc, cnorm, e);

    // --- layer 1 (GEMM overlaps CSR build; no dependency until agg) ---
    k_gemm<D1><<<cdiv(n, 64), T, 128 * D1 * sizeof(float)>>>(x, W1, xw1, n);
    k_agg1<<<cdiv((long long)n * 32, T), T>>>(xw1, csrc, cnorm, rstart, cnt, dinv,
                                              b1, gamma, beta, rmean, rvar, h, n);

    // --- layer 2 ---
    k_gemm<D2><<<cdiv(n, 64), T, 128 * D2 * sizeof(float)>>>(h, W2, xw2, n);
    k_agg2<<<cdiv((long long)n * 32, T), T>>>(xw2, csrc, cnorm, rstart, cnt, dinv,
                                              b2, out, n);
}

// round 6
// speedup vs baseline: 1.5005x; 1.5005x over previous
#include <cuda_runtime.h>

// ---------------------------------------------------------------------------
// GCN 2-layer, CSR-based (atomic-free aggregation), round 6:
//  - edges packed (src,norm) into one u64 -> single scattered store in fill,
//    single coalesced load in agg
//  - agg: warp/node, smem-staged indices, unroll-4 gathers (high MLP)
//  - GEMM: fma.rn.f32x2 packed fp32 (2 FMA/instr on Blackwell)
// edge_index is int32 [2, E] (JAX x64-off demotes int64).
// ---------------------------------------------------------------------------

#define N_MAX 50000
#define E_MAX 800000
#define D1 128
#define D2 64
#define SCAN_B 1024

__device__ float g_deg   [N_MAX];
__device__ float g_dinv  [N_MAX];
__device__ int   g_cnt   [N_MAX];
__device__ int   g_rstart[N_MAX];
__device__ int   g_cursor[N_MAX];
__device__ int   g_bsum  [64];
__device__ unsigned long long g_edge[E_MAX];   // (norm_bits<<32)|src
__device__ float g_xw1 [(size_t)N_MAX * D1];
__device__ float g_h   [(size_t)N_MAX * D1];
__device__ float g_xw2 [(size_t)N_MAX * D2];

// ---------------------------- f32x2 packed FMA -----------------------------

__device__ __forceinline__ void fma2(unsigned long long& d, unsigned long long a,
                                     unsigned long long b) {
    asm("fma.rn.f32x2 %0, %1, %2, %0;" : "+l"(d) : "l"(a), "l"(b));
}
__device__ __forceinline__ unsigned long long dup2(float s) {
    unsigned long long r;
    asm("mov.b64 %0, {%1, %1};" : "=l"(r) : "r"(__float_as_uint(s)));
    return r;
}

// ------------------------------ prep kernels -------------------------------

__global__ void k_init(float* deg, int* cnt, int n) {
    int i = blockIdx.x * blockDim.x + threadIdx.x;
    if (i < n) { deg[i] = 1.0f; cnt[i] = 0; }    // self-loop weight 1
}

__global__ void k_count(const int* __restrict__ ei, const float* __restrict__ w,
                        float* __restrict__ deg, int* __restrict__ cnt, int e) {
    int i = blockIdx.x * blockDim.x + threadIdx.x;
    if (i >= e) return;
    int d = ei[e + i];
    atomicAdd(&cnt[d], 1);
    atomicAdd(&deg[d], w[i]);
}

// exclusive scan of cnt -> rstart (3-phase)
__global__ void k_scan1(const int* __restrict__ cnt, int* __restrict__ rstart,
                        int* __restrict__ bsum, int n) {
    __shared__ int sh[SCAN_B];
    int i = blockIdx.x * SCAN_B + threadIdx.x;
    int v = (i < n) ? cnt[i] : 0;
    sh[threadIdx.x] = v;
    __syncthreads();
    for (int off = 1; off < SCAN_B; off <<= 1) {
        int t = (threadIdx.x >= off) ? sh[threadIdx.x - off] : 0;
        __syncthreads();
        sh[threadIdx.x] += t;
        __syncthreads();
    }
    if (i < n) rstart[i] = sh[threadIdx.x] - v;          // exclusive
    if (threadIdx.x == SCAN_B - 1) bsum[blockIdx.x] = sh[SCAN_B - 1];
}

__global__ void k_scan2(int* __restrict__ bsum, int nb) {
    __shared__ int sh[64];
    int v = (threadIdx.x < nb) ? bsum[threadIdx.x] : 0;
    sh[threadIdx.x] = v;
    __syncthreads();
    for (int off = 1; off < 64; off <<= 1) {
        int t = (threadIdx.x >= off) ? sh[threadIdx.x - off] : 0;
        __syncthreads();
        sh[threadIdx.x] += t;
        __syncthreads();
    }
    if (threadIdx.x < nb) bsum[threadIdx.x] = sh[threadIdx.x] - v;   // exclusive
}

// finalize rstart, init cursor, and compute dinv (merged)
__global__ void k_scan3(int* __restrict__ rstart, const int* __restrict__ bsum,
                        int* __restrict__ cursor,
                        const float* __restrict__ deg, float* __restrict__ dinv,
                        int n) {
    int i = blockIdx.x * blockDim.x + threadIdx.x;
    if (i < n) {
        int v = rstart[i] + bsum[i >> 10];
        rstart[i] = v;
        cursor[i] = v;
        float d = deg[i];
        dinv[i] = d > 0.f ? rsqrtf(d) : 0.f;
    }
}

__global__ void k_fill(const int* __restrict__ ei, const float* __restrict__ w,
                       const float* __restrict__ dinv,
                       int* __restrict__ cursor,
                       unsigned long long* __restrict__ edges, int e) {
    int i = blockIdx.x * blockDim.x + threadIdx.x;
    if (i >= e) return;
    int s = ei[i];
    int d = ei[e + i];
    float nv = dinv[s] * w[i] * dinv[d];
    int pos = atomicAdd(&cursor[d], 1);
    edges[pos] = (unsigned long long)(unsigned)s |
                 ((unsigned long long)__float_as_uint(nv) << 32);
}

// -------------------------------- GEMM -------------------------------------
// Y[n, COLS] = X[n, 128] @ W[128, COLS].  W in smem; f32x2 packed FMA.

template <int COLS>
__global__ void __launch_bounds__(256) k_gemm(const float* __restrict__ X,
                                              const float* __restrict__ W,
                                              float* __restrict__ Y, int n) {
    extern __shared__ float Wsh[];               // 128 * COLS floats
    constexpr int TPR = COLS / 4;                // threads per row (32 or 16)
    constexpr int RPI = 256 / TPR;               // rows per iteration (8 or 16)
    constexpr int ROWS_BLK = 64;
    for (int i = threadIdx.x; i < 128 * COLS / 4; i += 256)
        ((float4*)Wsh)[i] = ((const float4*)W)[i];
    __syncthreads();

    int col0 = (threadIdx.x % TPR) * 4;
    int rsub = threadIdx.x / TPR;
    int row0 = blockIdx.x * ROWS_BLK;
    int rend = min(row0 + ROWS_BLK, n);

    for (int r = row0 + rsub; r < rend; r += RPI) {
        const float4* xr = (const float4*)(X + (size_t)r * 128);
        unsigned long long acc01 = 0ull, acc23 = 0ull;  // {0.f,0.f} bit pattern
#pragma unroll
        for (int k4 = 0; k4 < 32; k4++) {
            float4 xv = xr[k4];
#pragma unroll
            for (int u = 0; u < 4; u++) {
                float xs = (u == 0) ? xv.x : (u == 1) ? xv.y : (u == 2) ? xv.z : xv.w;
                unsigned long long xx = dup2(xs);
                const unsigned long long* wp =
                    (const unsigned long long*)&Wsh[(k4 * 4 + u) * COLS + col0];
                fma2(acc01, xx, wp[0]);
                fma2(acc23, xx, wp[1]);
            }
        }
        unsigned long long* yo = (unsigned long long*)(Y + (size_t)r * COLS + col0);
        yo[0] = acc01;
        yo[1] = acc23;
    }
}

// --------------------------- CSR aggregation -------------------------------
// Warp per node. Phase A: coalesced load of up to 32 packed (src,norm) into
// smem. Phase B: unroll-4 gathers with register-resident indices (high MLP).

__global__ void __launch_bounds__(256) k_agg1(
        const float* __restrict__ xw, const unsigned long long* __restrict__ edges,
        const int* __restrict__ rstart, const int* __restrict__ cnt,
        const float* __restrict__ dinv,
        const float* __restrict__ b1, const float* __restrict__ gamma,
        const float* __restrict__ beta, const float* __restrict__ rmean,
        const float* __restrict__ rvar,
        float* __restrict__ h, int n) {
    __shared__ int   sh_s[8][32];
    __shared__ float sh_w[8][32];
    int node = (blockIdx.x * blockDim.x + threadIdx.x) >> 5;
    if (node >= n) return;
    int wid  = (threadIdx.x >> 5);
    int lane = threadIdx.x & 31;
    int s0 = rstart[node];
    int c  = cnt[node];

    float4 acc = make_float4(0.f, 0.f, 0.f, 0.f);
    for (int base = 0; base < c; base += 32) {
        int cc = min(c - base, 32);
        unsigned long long pk = 0;
        if (lane < cc) pk = edges[s0 + base + lane];
        sh_s[wid][lane] = (int)(unsigned)pk;
        sh_w[wid][lane] = __uint_as_float((unsigned)(pk >> 32));
        __syncwarp();
#pragma unroll 4
        for (int k = 0; k < cc; k++) {
            int   s  = sh_s[wid][k];
            float nv = sh_w[wid][k];
            float4 v = *(const float4*)(xw + (size_t)s * D1 + lane * 4);
            acc.x = fmaf(nv, v.x, acc.x); acc.y = fmaf(nv, v.y, acc.y);
            acc.z = fmaf(nv, v.z, acc.z); acc.w = fmaf(nv, v.w, acc.w);
        }
        __syncwarp();
    }

    float di = dinv[node];
    float sl = di * di;
    int c4 = lane * 4;
    float4 xv = *(const float4*)(xw + (size_t)node * D1 + c4);
    float4 bb = *(const float4*)(b1 + c4);
    float4 g  = *(const float4*)(gamma + c4);
    float4 be = *(const float4*)(beta + c4);
    float4 m  = *(const float4*)(rmean + c4);
    float4 vv = *(const float4*)(rvar + c4);
    float4 o;
    o.x = fmaxf((acc.x + sl * xv.x + bb.x - m.x) * rsqrtf(vv.x + 1e-5f) * g.x + be.x, 0.f);
    o.y = fmaxf((acc.y + sl * xv.y + bb.y - m.y) * rsqrtf(vv.y + 1e-5f) * g.y + be.y, 0.f);
    o.z = fmaxf((acc.z + sl * xv.z + bb.z - m.z) * rsqrtf(vv.z + 1e-5f) * g.z + be.z, 0.f);
    o.w = fmaxf((acc.w + sl * xv.w + bb.w - m.w) * rsqrtf(vv.w + 1e-5f) * g.w + be.w, 0.f);
    *(float4*)(h + (size_t)node * D1 + c4) = o;
}

__global__ void __launch_bounds__(256) k_agg2(
        const float* __restrict__ xw, const unsigned long long* __restrict__ edges,
        const int* __restrict__ rstart, const int* __restrict__ cnt,
        const float* __restrict__ dinv, const float* __restrict__ b2,
        float* __restrict__ out, int n) {
    __shared__ int   sh_s[8][32];
    __shared__ float sh_w[8][32];
    int node = (blockIdx.x * blockDim.x + threadIdx.x) >> 5;
    if (node >= n) return;
    int wid  = (threadIdx.x >> 5);
    int lane = threadIdx.x & 31;
    int s0 = rstart[node];
    int c  = cnt[node];

    float2 acc = make_float2(0.f, 0.f);
    for (int base = 0; base < c; base += 32) {
        int cc = min(c - base, 32);
        unsigned long long pk = 0;
        if (lane < cc) pk = edges[s0 + base + lane];
        sh_s[wid][lane] = (int)(unsigned)pk;
        sh_w[wid][lane] = __uint_as_float((unsigned)(pk >> 32));
        __syncwarp();
#pragma unroll 4
        for (int k = 0; k < cc; k++) {
            int   s  = sh_s[wid][k];
            float nv = sh_w[wid][k];
            float2 v = *(const float2*)(xw + (size_t)s * D2 + lane * 2);
            acc.x = fmaf(nv, v.x, acc.x); acc.y = fmaf(nv, v.y, acc.y);
        }
        __syncwarp();
    }

    float di = dinv[node];
    float sl = di * di;
    float2 xv = *(const float2*)(xw + (size_t)node * D2 + lane * 2);
    float2 bb = *(const float2*)(b2 + lane * 2);
    float2 o;
    o.x = acc.x + sl * xv.x + bb.x;
    o.y = acc.y + sl * xv.y + bb.y;
    *(float2*)(out + (size_t)node * D2 + lane * 2) = o;
}

// ------------------------------- launcher ----------------------------------

extern "C" void kernel_launch(void* const* d_in, const int* in_sizes, int n_in,
                              void* d_out, int out_size) {
    const float* x     = (const float*)d_in[0];
    const int*   ei    = (const int*)d_in[1];     // int32 [2, E]
    const float* ew    = (const float*)d_in[2];
    const float* W1    = (const float*)d_in[3];
    const float* b1    = (const float*)d_in[4];
    const float* gamma = (const float*)d_in[5];
    const float* beta  = (const float*)d_in[6];
    const float* rmean = (const float*)d_in[7];
    const float* rvar  = (const float*)d_in[8];
    const float* W2    = (const float*)d_in[9];
    const float* b2    = (const float*)d_in[10];
    float* out = (float*)d_out;

    int n = in_sizes[0] / D1;
    int e = in_sizes[2];

    float *deg, *dinv, *xw1, *h, *xw2;
    int *cnt, *rstart, *cursor, *bsum;
    unsigned long long* edges;
    cudaGetSymbolAddress((void**)&deg,    g_deg);
    cudaGetSymbolAddress((void**)&dinv,   g_dinv);
    cudaGetSymbolAddress((void**)&cnt,    g_cnt);
    cudaGetSymbolAddress((void**)&rstart, g_rstart);
    cudaGetSymbolAddress((void**)&cursor, g_cursor);
    cudaGetSymbolAddress((void**)&bsum,   g_bsum);
    cudaGetSymbolAddress((void**)&edges,  g_edge);
    cudaGetSymbolAddress((void**)&xw1,    g_xw1);
    cudaGetSymbolAddress((void**)&h,      g_h);
    cudaGetSymbolAddress((void**)&xw2,    g_xw2);

    cudaFuncSetAttribute(k_gemm<D1>, cudaFuncAttributeMaxDynamicSharedMemorySize,
                         128 * D1 * (int)sizeof(float));
    cudaFuncSetAttribute(k_gemm<D2>, cudaFuncAttributeMaxDynamicSharedMemorySize,
                         128 * D2 * (int)sizeof(float));

    const int T = 256;
    auto cdiv = [](long long a, long long b) { return (int)((a + b - 1) / b); };
    int nscan = cdiv(n, SCAN_B);

    // --- degree + CSR build (k_fill is launch #6 -> lands in the ncu window)
    k_init <<<cdiv(n, T), T>>>(deg, cnt, n);
    k_count<<<cdiv(e, T), T>>>(ei, ew, deg, cnt, e);
    k_scan1<<<nscan, SCAN_B>>>(cnt, rstart, bsum, n);
    k_scan2<<<1, 64>>>(bsum, nscan);
    k_scan3<<<cdiv(n, T), T>>>(rstart, bsum, cursor, deg, dinv, n);
    k_fill <<<cdiv(e, T), T>>>(ei, ew, dinv, cursor, edges, e);

    // --- layer 1 ---
    k_gemm<D1><<<cdiv(n, 64), T, 128 * D1 * sizeof(float)>>>(x, W1, xw1, n);
    k_agg1<<<cdiv((long long)n * 32, T), T>>>(xw1, edges, rstart, cnt, dinv,
                                              b1, gamma, beta, rmean, rvar, h, n);

    // --- layer 2 ---
    k_gemm<D2><<<cdiv(n, 64), T, 128 * D2 * sizeof(float)>>>(h, W2, xw2, n);
    k_agg2<<<cdiv((long long)n * 32, T), T>>>(xw2, edges, rstart, cnt, dinv,
                                              b2, out, n);
}